// round 15
// baseline (speedup 1.0000x reference)
#include <cuda_runtime.h>
#include <cuda_bf16.h>
#include <math.h>
#include <stdint.h>

// Problem constants
#define B_   2
#define S_   2048
#define D_   2048
#define H_   32
#define KV_  8
#define HD_  64
#define REP_ 4
#define BS_  (B_*S_)
#define NQKV (H_*HD_ + 2*KV_*HD_)      // 3072
#define NSM_ 148

// fp32 scratch: fused qkv projection output [BS_, 3072]
__device__ float g_qkv[(size_t)BS_*NQKV];

// bf16 hi/lo scratch
__device__ __nv_bfloat16 g_xh[(size_t)BS_*D_],  g_xl[(size_t)BS_*D_];
__device__ __nv_bfloat16 g_wqkvh[(size_t)NQKV*D_], g_wqkvl[(size_t)NQKV*D_];
__device__ __nv_bfloat16 g_woh[(size_t)D_*H_*HD_],  g_wol[(size_t)D_*H_*HD_];
__device__ __nv_bfloat16 g_qh[(size_t)BS_*H_*HD_],  g_ql[(size_t)BS_*H_*HD_];
__device__ __nv_bfloat16 g_kh[(size_t)BS_*KV_*HD_], g_kl[(size_t)BS_*KV_*HD_];
__device__ __nv_bfloat16 g_vh[(size_t)BS_*KV_*HD_], g_vl[(size_t)BS_*KV_*HD_];
__device__ __nv_bfloat16 g_oh[(size_t)BS_*H_*HD_],  g_ol[(size_t)BS_*H_*HD_];

// ---------------------------------------------------------------------------
__device__ __forceinline__ uint32_t smem_u32(const void* p) {
    uint32_t a;
    asm("{ .reg .u64 t; cvta.to.shared.u64 t, %1; cvt.u32.u64 %0, t; }"
        : "=r"(a) : "l"(p));
    return a;
}
__device__ __forceinline__ void cp16(uint32_t dst, const void* src) {
    asm volatile("cp.async.cg.shared.global [%0], [%1], 16;" :: "r"(dst), "l"(src));
}
__device__ __forceinline__ void ldmx4(uint32_t* r, uint32_t addr) {
    asm volatile("ldmatrix.sync.aligned.m8n8.x4.shared.b16 {%0,%1,%2,%3}, [%4];"
                 : "=r"(r[0]), "=r"(r[1]), "=r"(r[2]), "=r"(r[3]) : "r"(addr));
}
__device__ __forceinline__ void ldmx4t(uint32_t* r, uint32_t addr) {
    asm volatile("ldmatrix.sync.aligned.m8n8.x4.trans.shared.b16 {%0,%1,%2,%3}, [%4];"
                 : "=r"(r[0]), "=r"(r[1]), "=r"(r[2]), "=r"(r[3]) : "r"(addr));
}
__device__ __forceinline__ void mma16816(float* c, const uint32_t* a,
                                         uint32_t b0, uint32_t b1) {
    asm volatile("mma.sync.aligned.m16n8k16.row.col.f32.bf16.bf16.f32 "
                 "{%0,%1,%2,%3}, {%4,%5,%6,%7}, {%8,%9}, {%0,%1,%2,%3};"
                 : "+f"(c[0]), "+f"(c[1]), "+f"(c[2]), "+f"(c[3])
                 : "r"(a[0]), "r"(a[1]), "r"(a[2]), "r"(a[3]), "r"(b0), "r"(b1));
}
__device__ __forceinline__ uint32_t pack2(float lo, float hi) {
    __nv_bfloat162 t = __floats2bfloat162_rn(lo, hi);
    uint32_t u;
    memcpy(&u, &t, 4);
    return u;
}
__device__ __forceinline__ float bflo(uint32_t u) { return __uint_as_float(u << 16); }
__device__ __forceinline__ float bfhi(uint32_t u) { return __uint_as_float(u & 0xffff0000u); }
__device__ __forceinline__ uint32_t sw64(uint32_t off) {
    return off ^ ((off >> 3) & 0x30u);
}

// ---------------------------------------------------------------------------
// fp32 -> bf16 hi/lo split (dense, grid-stride x4)
// ---------------------------------------------------------------------------
__global__ void split4_kernel(const float4* __restrict__ in,
                              uint2* __restrict__ hi, uint2* __restrict__ lo, int n4) {
    const int span = gridDim.x * blockDim.x;
    int i0 = blockIdx.x * blockDim.x + threadIdx.x;
#pragma unroll 4
    for (int i = i0; i < n4; i += span) {
        float4 x = in[i];
        __nv_bfloat16 h[4], l[4];
        float xs[4] = {x.x, x.y, x.z, x.w};
#pragma unroll
        for (int j = 0; j < 4; j++) {
            h[j] = __float2bfloat16(xs[j]);
            l[j] = __float2bfloat16(xs[j] - __bfloat162float(h[j]));
        }
        uint2 hv, lv;
        memcpy(&hv, h, 8);
        memcpy(&lv, l, 8);
        hi[i] = hv;
        lo[i] = lv;
    }
}

// ---------------------------------------------------------------------------
// RoPE + scale + split, strided column slice of g_qkv (grid-stride x4)
// ---------------------------------------------------------------------------
__global__ void rope_split_strided(const float* __restrict__ t, const float* __restrict__ fc,
                                   uint32_t* __restrict__ th, uint32_t* __restrict__ tl,
                                   int NH, int RS, int CB, float scale, int total) {
    const int span = gridDim.x * blockDim.x;
    int i0 = blockIdx.x * blockDim.x + threadIdx.x;
    const int per = NH * 32;
#pragma unroll 4
    for (int idx = i0; idx < total; idx += span) {
        int bs = idx / per, pr = idx - bs * per;
        int p = pr & 31;
        int s = bs & (S_ - 1);
        float c  = fc[(s * 32 + p) * 2 + 0];
        float sn = fc[(s * 32 + p) * 2 + 1];
        float2 v = *(const float2*)(t + (size_t)bs * RS + CB + pr * 2);
        float r0 = (v.x * c - v.y * sn) * scale;
        float r1 = (v.x * sn + v.y * c) * scale;
        uint32_t hp = pack2(r0, r1);
        uint32_t lp = pack2(r0 - bflo(hp), r1 - bfhi(hp));
        th[idx] = hp;
        tl[idx] = lp;
    }
}

__global__ void split_strided(const float* __restrict__ t,
                              uint32_t* __restrict__ th, uint32_t* __restrict__ tl,
                              int NH, int RS, int CB, int total) {
    const int span = gridDim.x * blockDim.x;
    int i0 = blockIdx.x * blockDim.x + threadIdx.x;
    const int per = NH * 32;
#pragma unroll 4
    for (int idx = i0; idx < total; idx += span) {
        int bs = idx / per, pr = idx - bs * per;
        float2 v = *(const float2*)(t + (size_t)bs * RS + CB + pr * 2);
        uint32_t hp = pack2(v.x, v.y);
        uint32_t lp = pack2(v.x - bflo(hp), v.y - bfhi(hp));
        th[idx] = hp;
        tl[idx] = lp;
    }
}

// ---------------------------------------------------------------------------
// bf16x3 PERSISTENT GEMM via mma.sync.
// CTA tile 128x128, 256 threads (8 warps, 2Mx4N, warp 64x32), BK=32.
// SW64 smem, 3 stages = 98304 B -> depth 3 AND 2 CTAs/SM.
// Grid-stride loop over output tiles (no wave-quantization tail).
// ---------------------------------------------------------------------------
#define TQ_   (128 * 64)
#define STAGE_B  (4 * TQ_)               // 32768
#define GEMM_STAGES 3
#define GEMM_SMEM (GEMM_STAGES * STAGE_B)   // 98304 -> 2 CTAs/SM

__global__ __launch_bounds__(256, 2) void gemm_mma(
    const __nv_bfloat16* __restrict__ Ah, const __nv_bfloat16* __restrict__ Al,
    const __nv_bfloat16* __restrict__ Bh, const __nv_bfloat16* __restrict__ Bl,
    float* __restrict__ C, int M, int N, int K) {
    extern __shared__ char sm[];
    const uint32_t sbase = smem_u32(sm);

    const int tid  = threadIdx.x;
    const int wid  = tid >> 5;
    const int lane = tid & 31;
    const int wm   = wid >> 2;
    const int wn   = wid & 3;
    const int g = lane >> 3, r8 = lane & 7;
    const int NS = K >> 5;
    const int ntn = N >> 7;
    const int nTiles = (M >> 7) * ntn;

    for (int tile = blockIdx.x; tile < nTiles; tile += gridDim.x) {
        const int m0 = (tile / ntn) << 7;
        const int n0 = (tile % ntn) << 7;

        const __nv_bfloat16* srcs[4] = {Ah, Al, Bh, Bl};
        const int rows0[4] = {m0, m0, n0, n0};

        auto load_stage = [&](int j) {
            uint32_t sb = sbase + (uint32_t)(j % GEMM_STAGES) * STAGE_B;
            int k0 = j << 5;
#pragma unroll
            for (int t = 0; t < 4; t++) {
                const __nv_bfloat16* src = srcs[t] + (size_t)rows0[t] * K + k0;
                uint32_t tb = sb + t * TQ_;
#pragma unroll
                for (int it = 0; it < 2; it++) {
                    int ch = tid + it * 256;
                    int r = ch >> 2, c4 = ch & 3;
                    cp16(tb + sw64((uint32_t)(r * 64 + c4 * 16)),
                         src + (size_t)r * K + c4 * 8);
                }
            }
            asm volatile("cp.async.commit_group;" ::: "memory");
        };

        // previous tile's last MMAs may still read buffer 0 — order before refill
        __syncthreads();

        float acc[4][4][4];
#pragma unroll
        for (int i = 0; i < 4; i++)
#pragma unroll
            for (int j = 0; j < 4; j++)
#pragma unroll
                for (int c = 0; c < 4; c++) acc[i][j][c] = 0.0f;

        load_stage(0);
        load_stage(1);

        for (int j = 0; j < NS; j++) {
            if (j + 1 < NS) {
                asm volatile("cp.async.wait_group 1;" ::: "memory");
            } else {
                asm volatile("cp.async.wait_group 0;" ::: "memory");
            }
            __syncthreads();
            if (j + 2 < NS) load_stage(j + 2);

            uint32_t sb = sbase + (uint32_t)(j % GEMM_STAGES) * STAGE_B;
            uint32_t Ahb = sb, Alb = sb + TQ_, Bhb = sb + 2 * TQ_, Blb = sb + 3 * TQ_;

#pragma unroll
            for (int ks = 0; ks < 2; ks++) {
                uint32_t AH[4][4], AL[4][4];
#pragma unroll
                for (int mt = 0; mt < 4; mt++) {
                    int row = wm * 64 + mt * 16 + (g & 1) * 8 + r8;
                    uint32_t off = sw64((uint32_t)(row * 64 + ks * 32 + (g >> 1) * 16));
                    ldmx4(AH[mt], Ahb + off);
                    ldmx4(AL[mt], Alb + off);
                }
#pragma unroll
                for (int np = 0; np < 2; np++) {
                    int row = wn * 32 + np * 16 + (g >> 1) * 8 + r8;
                    uint32_t off = sw64((uint32_t)(row * 64 + ks * 32 + (g & 1) * 16));
                    uint32_t BH[4], BL[4];
                    ldmx4(BH, Bhb + off);
                    ldmx4(BL, Blb + off);
#pragma unroll
                    for (int mt = 0; mt < 4; mt++) {
                        float* c0 = acc[mt][2 * np];
                        float* c1 = acc[mt][2 * np + 1];
                        mma16816(c0, AH[mt], BH[0], BH[1]);
                        mma16816(c0, AH[mt], BL[0], BL[1]);
                        mma16816(c0, AL[mt], BH[0], BH[1]);
                        mma16816(c1, AH[mt], BH[2], BH[3]);
                        mma16816(c1, AH[mt], BL[2], BL[3]);
                        mma16816(c1, AL[mt], BH[2], BH[3]);
                    }
                }
            }
        }

        const int er = lane >> 2, ec = (lane & 3) * 2;
#pragma unroll
        for (int mt = 0; mt < 4; mt++) {
#pragma unroll
            for (int nt = 0; nt < 4; nt++) {
                int row = m0 + wm * 64 + mt * 16 + er;
                int col = n0 + wn * 32 + nt * 8 + ec;
                float* c = acc[mt][nt];
                *(float2*)(C + (size_t)row * N + col)       = make_float2(c[0], c[1]);
                *(float2*)(C + (size_t)(row + 8) * N + col) = make_float2(c[2], c[3]);
            }
        }
    }
}

// ---------------------------------------------------------------------------
// Tensor-core causal GQA flash attention (R14 version).
// 64 queries/CTA (4 warps), 3-stage KV pipeline with Q overlaid on stage 2.
// 98304 B -> 2 CTAs/SM.
// ---------------------------------------------------------------------------
#define AT_TILE 8192
#define AT_STAGE (4 * AT_TILE)             // 32768
#define AT_STAGES 3
#define AT_SMEM (AT_STAGES * AT_STAGE)     // 98304

__global__ __launch_bounds__(128, 2) void attn_mma(
    const __nv_bfloat16* __restrict__ qh, const __nv_bfloat16* __restrict__ ql,
    const __nv_bfloat16* __restrict__ kh, const __nv_bfloat16* __restrict__ kl,
    const __nv_bfloat16* __restrict__ vh, const __nv_bfloat16* __restrict__ vl,
    __nv_bfloat16* __restrict__ oh, __nv_bfloat16* __restrict__ ol) {
    extern __shared__ char sm[];
    const uint32_t sb = smem_u32(sm);
    const int tid = threadIdx.x, wid = tid >> 5, lane = tid & 31;
    const int qblk = gridDim.x - 1 - blockIdx.x;
    const int h = blockIdx.y, b = blockIdx.z, g = h >> 2;
    const int q0 = qblk * 64;
    const uint32_t sQh = sb + 2 * AT_STAGE;
    const uint32_t sQl = sQh + AT_TILE;
    const int nT = q0 / 64 + 1;
    const int g2 = lane >> 3, r8v = lane & 7;

    auto load_kv = [&](int t) {
        uint32_t s0 = sb + (uint32_t)(t % AT_STAGES) * AT_STAGE;
        const __nv_bfloat16* srcs[4] = {kh, kl, vh, vl};
#pragma unroll
        for (int a = 0; a < 4; a++) {
            const __nv_bfloat16* src = srcs[a];
            uint32_t tb = s0 + a * AT_TILE;
#pragma unroll
            for (int it = 0; it < 4; it++) {
                int i = tid + it * 128;
                int r = i >> 3, c = i & 7;
                cp16(tb + r * 128 + ((c ^ (r & 7)) * 16),
                     src + ((size_t)(b * S_ + t * 64 + r) * KV_ + g) * HD_ + c * 8);
            }
        }
        asm volatile("cp.async.commit_group;" ::: "memory");
    };
    load_kv(0);
    if (nT > 1) load_kv(1);

    for (int i = tid; i < 512; i += 128) {
        int r = i >> 3, c = i & 7;
        size_t gidx = ((size_t)(b * S_ + q0 + r) * H_ + h) * HD_ + c * 8;
        uint32_t off = r * 128 + ((c ^ (r & 7)) * 16);
        *(uint4*)(sm + (sQh - sb) + off) = *(const uint4*)(qh + gidx);
        *(uint4*)(sm + (sQl - sb) + off) = *(const uint4*)(ql + gidx);
    }
    __syncthreads();

    uint32_t AH[4][4], AL[4][4];
#pragma unroll
    for (int ks = 0; ks < 4; ks++) {
        int row = wid * 16 + (g2 & 1) * 8 + r8v;
        int ch = ks * 2 + (g2 >> 1);
        uint32_t off = row * 128 + ((ch ^ (row & 7)) * 16);
        ldmx4(AH[ks], sQh + off);
        ldmx4(AL[ks], sQl + off);
    }

    float accO[8][4];
#pragma unroll
    for (int i = 0; i < 8; i++)
#pragma unroll
        for (int c = 0; c < 4; c++) accO[i][c] = 0.0f;
    float mrow0 = -1e30f, mrow1 = -1e30f, lrow0 = 0.0f, lrow1 = 0.0f;
    const int qrow0 = q0 + wid * 16 + (lane >> 2);

    for (int t = 0; t < nT; t++) {
        if (t + 1 < nT) {
            asm volatile("cp.async.wait_group 1;" ::: "memory");
        } else {
            asm volatile("cp.async.wait_group 0;" ::: "memory");
        }
        __syncthreads();
        if (t + 2 < nT) load_kv(t + 2);

        uint32_t st = sb + (uint32_t)(t % AT_STAGES) * AT_STAGE;
        uint32_t sKh = st, sKl = st + AT_TILE, sVh = st + 2 * AT_TILE, sVl = st + 3 * AT_TILE;

        float sc[8][4];
#pragma unroll
        for (int i = 0; i < 8; i++)
#pragma unroll
            for (int c = 0; c < 4; c++) sc[i][c] = 0.0f;
#pragma unroll
        for (int ks = 0; ks < 4; ks++) {
            uint32_t KH[4][4], KL[4][4];
#pragma unroll
            for (int np = 0; np < 4; np++) {
                int row = np * 16 + (g2 >> 1) * 8 + r8v;
                int ch = ks * 2 + (g2 & 1);
                uint32_t off = row * 128 + ((ch ^ (row & 7)) * 16);
                ldmx4(KH[np], sKh + off);
                ldmx4(KL[np], sKl + off);
            }
#pragma unroll
            for (int np = 0; np < 4; np++) {
                mma16816(sc[2 * np],     AH[ks], KH[np][0], KH[np][1]);
                mma16816(sc[2 * np],     AH[ks], KL[np][0], KL[np][1]);
                mma16816(sc[2 * np],     AL[ks], KH[np][0], KH[np][1]);
                mma16816(sc[2 * np + 1], AH[ks], KH[np][2], KH[np][3]);
                mma16816(sc[2 * np + 1], AH[ks], KL[np][2], KL[np][3]);
                mma16816(sc[2 * np + 1], AL[ks], KH[np][2], KH[np][3]);
            }
        }

        if (t == nT - 1) {
#pragma unroll
            for (int nt = 0; nt < 8; nt++) {
                int key = t * 64 + nt * 8 + (lane & 3) * 2;
                if (key     > qrow0)     sc[nt][0] = -1e30f;
                if (key + 1 > qrow0)     sc[nt][1] = -1e30f;
                if (key     > qrow0 + 8) sc[nt][2] = -1e30f;
                if (key + 1 > qrow0 + 8) sc[nt][3] = -1e30f;
            }
        }

        float mx0 = -1e30f, mx1 = -1e30f;
#pragma unroll
        for (int nt = 0; nt < 8; nt++) {
            mx0 = fmaxf(mx0, fmaxf(sc[nt][0], sc[nt][1]));
            mx1 = fmaxf(mx1, fmaxf(sc[nt][2], sc[nt][3]));
        }
        mx0 = fmaxf(mx0, __shfl_xor_sync(0xffffffffu, mx0, 1));
        mx0 = fmaxf(mx0, __shfl_xor_sync(0xffffffffu, mx0, 2));
        mx1 = fmaxf(mx1, __shfl_xor_sync(0xffffffffu, mx1, 1));
        mx1 = fmaxf(mx1, __shfl_xor_sync(0xffffffffu, mx1, 2));
        float mn0 = fmaxf(mrow0, mx0), mn1 = fmaxf(mrow1, mx1);
        float cor0 = __expf(mrow0 - mn0), cor1 = __expf(mrow1 - mn1);
        mrow0 = mn0; mrow1 = mn1;
        lrow0 *= cor0; lrow1 *= cor1;
#pragma unroll
        for (int nt = 0; nt < 8; nt++) {
            accO[nt][0] *= cor0; accO[nt][1] *= cor0;
            accO[nt][2] *= cor1; accO[nt][3] *= cor1;
        }

        uint32_t PH[4][4], PL[4][4];
#pragma unroll
        for (int nt = 0; nt < 8; nt++) {
            float e0 = __expf(sc[nt][0] - mrow0);
            float e1 = __expf(sc[nt][1] - mrow0);
            float e2 = __expf(sc[nt][2] - mrow1);
            float e3 = __expf(sc[nt][3] - mrow1);
            lrow0 += e0 + e1; lrow1 += e2 + e3;
            uint32_t h01 = pack2(e0, e1);
            uint32_t h23 = pack2(e2, e3);
            uint32_t l01 = pack2(e0 - bflo(h01), e1 - bfhi(h01));
            uint32_t l23 = pack2(e2 - bflo(h23), e3 - bfhi(h23));
            PH[nt >> 1][(nt & 1) * 2 + 0] = h01;
            PH[nt >> 1][(nt & 1) * 2 + 1] = h23;
            PL[nt >> 1][(nt & 1) * 2 + 0] = l01;
            PL[nt >> 1][(nt & 1) * 2 + 1] = l23;
        }

#pragma unroll
        for (int ks = 0; ks < 4; ks++) {
            uint32_t VH[4][4], VL[4][4];
#pragma unroll
            for (int np = 0; np < 4; np++) {
                int krow = ks * 16 + (g2 & 1) * 8 + r8v;
                int ch = np * 2 + (g2 >> 1);
                uint32_t off = krow * 128 + ((ch ^ (krow & 7)) * 16);
                ldmx4t(VH[np], sVh + off);
                ldmx4t(VL[np], sVl + off);
            }
#pragma unroll
            for (int np = 0; np < 4; np++) {
                mma16816(accO[2 * np],     PH[ks], VH[np][0], VH[np][1]);
                mma16816(accO[2 * np],     PL[ks], VH[np][0], VH[np][1]);
                mma16816(accO[2 * np],     PH[ks], VL[np][0], VL[np][1]);
                mma16816(accO[2 * np + 1], PH[ks], VH[np][2], VH[np][3]);
                mma16816(accO[2 * np + 1], PL[ks], VH[np][2], VH[np][3]);
                mma16816(accO[2 * np + 1], PH[ks], VL[np][2], VL[np][3]);
            }
        }
    }

    lrow0 += __shfl_xor_sync(0xffffffffu, lrow0, 1);
    lrow0 += __shfl_xor_sync(0xffffffffu, lrow0, 2);
    lrow1 += __shfl_xor_sync(0xffffffffu, lrow1, 1);
    lrow1 += __shfl_xor_sync(0xffffffffu, lrow1, 2);
    float inv0 = 1.0f / lrow0, inv1 = 1.0f / lrow1;

    const int row0 = q0 + wid * 16 + (lane >> 2);
    const int row1 = row0 + 8;
#pragma unroll
    for (int nt = 0; nt < 8; nt++) {
        int col = nt * 8 + (lane & 3) * 2;
        size_t i0 = ((size_t)(b * S_ + row0) * H_ + h) * HD_ + col;
        size_t i1 = ((size_t)(b * S_ + row1) * H_ + h) * HD_ + col;
        float v0 = accO[nt][0] * inv0, v1 = accO[nt][1] * inv0;
        float v2 = accO[nt][2] * inv1, v3 = accO[nt][3] * inv1;
        uint32_t h01 = pack2(v0, v1);
        uint32_t l01 = pack2(v0 - bflo(h01), v1 - bfhi(h01));
        uint32_t h23 = pack2(v2, v3);
        uint32_t l23 = pack2(v2 - bflo(h23), v3 - bfhi(h23));
        *(uint32_t*)(oh + i0) = h01;
        *(uint32_t*)(ol + i0) = l01;
        *(uint32_t*)(oh + i1) = h23;
        *(uint32_t*)(ol + i1) = l23;
    }
}

// ---------------------------------------------------------------------------
extern "C" void kernel_launch(void* const* d_in, const int* in_sizes, int n_in,
                              void* d_out, int out_size) {
    const float* x  = (const float*)d_in[0];
    const float* fc = (const float*)d_in[1];
    const float* wq = (const float*)d_in[2];
    const float* wk = (const float*)d_in[3];
    const float* wv = (const float*)d_in[4];
    const float* wo = (const float*)d_in[5];
    float* out = (float*)d_out;

    float* qkv;
    cudaGetSymbolAddress((void**)&qkv, g_qkv);
    __nv_bfloat16 *xh, *xl, *wqkvh, *wqkvl, *woh, *wol;
    __nv_bfloat16 *qh, *ql, *khp, *klp, *vhp, *vlp, *oh, *ol;
    cudaGetSymbolAddress((void**)&xh, g_xh);       cudaGetSymbolAddress((void**)&xl, g_xl);
    cudaGetSymbolAddress((void**)&wqkvh, g_wqkvh); cudaGetSymbolAddress((void**)&wqkvl, g_wqkvl);
    cudaGetSymbolAddress((void**)&woh, g_woh);     cudaGetSymbolAddress((void**)&wol, g_wol);
    cudaGetSymbolAddress((void**)&qh, g_qh);       cudaGetSymbolAddress((void**)&ql, g_ql);
    cudaGetSymbolAddress((void**)&khp, g_kh);      cudaGetSymbolAddress((void**)&klp, g_kl);
    cudaGetSymbolAddress((void**)&vhp, g_vh);      cudaGetSymbolAddress((void**)&vlp, g_vl);
    cudaGetSymbolAddress((void**)&oh, g_oh);       cudaGetSymbolAddress((void**)&ol, g_ol);

    cudaFuncSetAttribute(gemm_mma, cudaFuncAttributeMaxDynamicSharedMemorySize, GEMM_SMEM);
    cudaFuncSetAttribute(attn_mma, cudaFuncAttributeMaxDynamicSharedMemorySize, AT_SMEM);

    auto split = [&](const float* src, __nv_bfloat16* h, __nv_bfloat16* l, size_t n) {
        int n4 = (int)(n / 4);
        int grid = (n4 + 1023) / 1024;
        split4_kernel<<<grid, 256>>>((const float4*)src, (uint2*)h, (uint2*)l, n4);
    };
    split(x,  xh,  xl,  (size_t)BS_ * D_);
    split(wq, wqkvh,                           wqkvl,                           (size_t)H_*HD_*D_);
    split(wk, wqkvh + (size_t)H_*HD_*D_,       wqkvl + (size_t)H_*HD_*D_,       (size_t)KV_*HD_*D_);
    split(wv, wqkvh + (size_t)(H_+KV_)*HD_*D_, wqkvl + (size_t)(H_+KV_)*HD_*D_, (size_t)KV_*HD_*D_);
    split(wo, woh, wol, (size_t)D_ * H_ * HD_);

    // Fused QKV projection — persistent grid (no wave tail)
    {
        int nTiles = (BS_ / 128) * (NQKV / 128);          // 768
        int grid = min(nTiles, 2 * NSM_);                 // 296
        gemm_mma<<<grid, 256, GEMM_SMEM>>>(xh, xl, wqkvh, wqkvl, qkv, BS_, NQKV, D_);
    }

    // RoPE + split (grid-stride x4)
    {
        int qpairs = BS_ * H_ * 32;
        int kpairs = BS_ * KV_ * 32;
        rope_split_strided<<<(qpairs + 1023) / 1024, 256>>>(qkv, fc, (uint32_t*)qh, (uint32_t*)ql,
                                                            H_, NQKV, 0, 0.125f, qpairs);
        rope_split_strided<<<(kpairs + 1023) / 1024, 256>>>(qkv, fc, (uint32_t*)khp, (uint32_t*)klp,
                                                            KV_, NQKV, H_*HD_, 1.0f, kpairs);
        split_strided<<<(kpairs + 1023) / 1024, 256>>>(qkv, (uint32_t*)vhp, (uint32_t*)vlp,
                                                       KV_, NQKV, (H_+KV_)*HD_, kpairs);
    }

    // Tensor-core flash attention -> oh/ol
    attn_mma<<<dim3(S_/64, H_, B_), 128, AT_SMEM>>>(qh, ql, khp, klp, vhp, vlp, oh, ol);

    // Output projection — persistent grid
    {
        int nTiles = (BS_ / 128) * (D_ / 128);            // 512
        int grid = min(nTiles, 2 * NSM_);                 // 296
        gemm_mma<<<grid, 256, GEMM_SMEM>>>(oh, ol, woh, wol, out, BS_, D_, D_);
    }
}

// round 16
// speedup vs baseline: 1.0006x; 1.0006x over previous
#include <cuda_runtime.h>
#include <cuda_bf16.h>
#include <math.h>
#include <stdint.h>

// Problem constants
#define B_   2
#define S_   2048
#define D_   2048
#define H_   32
#define KV_  8
#define HD_  64
#define REP_ 4
#define BS_  (B_*S_)
#define NQKV (H_*HD_ + 2*KV_*HD_)      // 3072

// fp32 scratch: fused qkv projection output [BS_, 3072]
__device__ float g_qkv[(size_t)BS_*NQKV];

// bf16 hi/lo scratch
__device__ __nv_bfloat16 g_xh[(size_t)BS_*D_],  g_xl[(size_t)BS_*D_];
__device__ __nv_bfloat16 g_wqkvh[(size_t)NQKV*D_], g_wqkvl[(size_t)NQKV*D_];
__device__ __nv_bfloat16 g_woh[(size_t)D_*H_*HD_],  g_wol[(size_t)D_*H_*HD_];
__device__ __nv_bfloat16 g_qh[(size_t)BS_*H_*HD_],  g_ql[(size_t)BS_*H_*HD_];
__device__ __nv_bfloat16 g_kh[(size_t)BS_*KV_*HD_], g_kl[(size_t)BS_*KV_*HD_];
__device__ __nv_bfloat16 g_vh[(size_t)BS_*KV_*HD_], g_vl[(size_t)BS_*KV_*HD_];
__device__ __nv_bfloat16 g_oh[(size_t)BS_*H_*HD_],  g_ol[(size_t)BS_*H_*HD_];

// ---------------------------------------------------------------------------
__device__ __forceinline__ uint32_t smem_u32(const void* p) {
    uint32_t a;
    asm("{ .reg .u64 t; cvta.to.shared.u64 t, %1; cvt.u32.u64 %0, t; }"
        : "=r"(a) : "l"(p));
    return a;
}
__device__ __forceinline__ void cp16(uint32_t dst, const void* src) {
    asm volatile("cp.async.cg.shared.global [%0], [%1], 16;" :: "r"(dst), "l"(src));
}
__device__ __forceinline__ void ldmx4(uint32_t* r, uint32_t addr) {
    asm volatile("ldmatrix.sync.aligned.m8n8.x4.shared.b16 {%0,%1,%2,%3}, [%4];"
                 : "=r"(r[0]), "=r"(r[1]), "=r"(r[2]), "=r"(r[3]) : "r"(addr));
}
__device__ __forceinline__ void ldmx4t(uint32_t* r, uint32_t addr) {
    asm volatile("ldmatrix.sync.aligned.m8n8.x4.trans.shared.b16 {%0,%1,%2,%3}, [%4];"
                 : "=r"(r[0]), "=r"(r[1]), "=r"(r[2]), "=r"(r[3]) : "r"(addr));
}
__device__ __forceinline__ void mma16816(float* c, const uint32_t* a,
                                         uint32_t b0, uint32_t b1) {
    asm volatile("mma.sync.aligned.m16n8k16.row.col.f32.bf16.bf16.f32 "
                 "{%0,%1,%2,%3}, {%4,%5,%6,%7}, {%8,%9}, {%0,%1,%2,%3};"
                 : "+f"(c[0]), "+f"(c[1]), "+f"(c[2]), "+f"(c[3])
                 : "r"(a[0]), "r"(a[1]), "r"(a[2]), "r"(a[3]), "r"(b0), "r"(b1));
}
__device__ __forceinline__ uint32_t pack2(float lo, float hi) {
    __nv_bfloat162 t = __floats2bfloat162_rn(lo, hi);
    uint32_t u;
    memcpy(&u, &t, 4);
    return u;
}
__device__ __forceinline__ float bflo(uint32_t u) { return __uint_as_float(u << 16); }
__device__ __forceinline__ float bfhi(uint32_t u) { return __uint_as_float(u & 0xffff0000u); }
__device__ __forceinline__ uint32_t sw64(uint32_t off) {
    return off ^ ((off >> 3) & 0x30u);
}

// ---------------------------------------------------------------------------
// fp32 -> bf16 hi/lo split (dense, grid-stride x4)
// ---------------------------------------------------------------------------
__global__ void split4_kernel(const float4* __restrict__ in,
                              uint2* __restrict__ hi, uint2* __restrict__ lo, int n4) {
    const int span = gridDim.x * blockDim.x;
    int i0 = blockIdx.x * blockDim.x + threadIdx.x;
#pragma unroll 4
    for (int i = i0; i < n4; i += span) {
        float4 x = in[i];
        __nv_bfloat16 h[4], l[4];
        float xs[4] = {x.x, x.y, x.z, x.w};
#pragma unroll
        for (int j = 0; j < 4; j++) {
            h[j] = __float2bfloat16(xs[j]);
            l[j] = __float2bfloat16(xs[j] - __bfloat162float(h[j]));
        }
        uint2 hv, lv;
        memcpy(&hv, h, 8);
        memcpy(&lv, l, 8);
        hi[i] = hv;
        lo[i] = lv;
    }
}

// ---------------------------------------------------------------------------
// RoPE + scale + split, strided column slice of g_qkv (grid-stride x4)
// ---------------------------------------------------------------------------
__global__ void rope_split_strided(const float* __restrict__ t, const float* __restrict__ fc,
                                   uint32_t* __restrict__ th, uint32_t* __restrict__ tl,
                                   int NH, int RS, int CB, float scale, int total) {
    const int span = gridDim.x * blockDim.x;
    int i0 = blockIdx.x * blockDim.x + threadIdx.x;
    const int per = NH * 32;
#pragma unroll 4
    for (int idx = i0; idx < total; idx += span) {
        int bs = idx / per, pr = idx - bs * per;
        int p = pr & 31;
        int s = bs & (S_ - 1);
        float c  = fc[(s * 32 + p) * 2 + 0];
        float sn = fc[(s * 32 + p) * 2 + 1];
        float2 v = *(const float2*)(t + (size_t)bs * RS + CB + pr * 2);
        float r0 = (v.x * c - v.y * sn) * scale;
        float r1 = (v.x * sn + v.y * c) * scale;
        uint32_t hp = pack2(r0, r1);
        uint32_t lp = pack2(r0 - bflo(hp), r1 - bfhi(hp));
        th[idx] = hp;
        tl[idx] = lp;
    }
}

__global__ void split_strided(const float* __restrict__ t,
                              uint32_t* __restrict__ th, uint32_t* __restrict__ tl,
                              int NH, int RS, int CB, int total) {
    const int span = gridDim.x * blockDim.x;
    int i0 = blockIdx.x * blockDim.x + threadIdx.x;
    const int per = NH * 32;
#pragma unroll 4
    for (int idx = i0; idx < total; idx += span) {
        int bs = idx / per, pr = idx - bs * per;
        float2 v = *(const float2*)(t + (size_t)bs * RS + CB + pr * 2);
        uint32_t hp = pack2(v.x, v.y);
        uint32_t lp = pack2(v.x - bflo(hp), v.y - bfhi(hp));
        th[idx] = hp;
        tl[idx] = lp;
    }
}

// ---------------------------------------------------------------------------
// bf16x3 GEMM via mma.sync (R13/R14 version — best).
// CTA tile 128x128, 256 threads (8 warps, 2Mx4N, warp 64x32), BK=32.
// SW64 smem, 3 stages = 98304 B -> depth 3 AND 2 CTAs/SM. Plain grid.
// ---------------------------------------------------------------------------
#define TQ_   (128 * 64)
#define STAGE_B  (4 * TQ_)               // 32768
#define GEMM_STAGES 3
#define GEMM_SMEM (GEMM_STAGES * STAGE_B)   // 98304

__global__ __launch_bounds__(256, 2) void gemm_mma(
    const __nv_bfloat16* __restrict__ Ah, const __nv_bfloat16* __restrict__ Al,
    const __nv_bfloat16* __restrict__ Bh, const __nv_bfloat16* __restrict__ Bl,
    float* __restrict__ C, int M, int N, int K) {
    extern __shared__ char sm[];
    const uint32_t sbase = smem_u32(sm);

    const int tid  = threadIdx.x;
    const int wid  = tid >> 5;
    const int lane = tid & 31;
    const int wm   = wid >> 2;
    const int wn   = wid & 3;
    const int m0   = blockIdx.y << 7;
    const int n0   = blockIdx.x << 7;

    const __nv_bfloat16* srcs[4] = {Ah, Al, Bh, Bl};
    const int rows0[4] = {m0, m0, n0, n0};

    auto load_stage = [&](int j) {
        uint32_t sb = sbase + (uint32_t)(j % GEMM_STAGES) * STAGE_B;
        int k0 = j << 5;
#pragma unroll
        for (int t = 0; t < 4; t++) {
            const __nv_bfloat16* src = srcs[t] + (size_t)rows0[t] * K + k0;
            uint32_t tb = sb + t * TQ_;
#pragma unroll
            for (int it = 0; it < 2; it++) {
                int ch = tid + it * 256;
                int r = ch >> 2, c4 = ch & 3;
                cp16(tb + sw64((uint32_t)(r * 64 + c4 * 16)),
                     src + (size_t)r * K + c4 * 8);
            }
        }
        asm volatile("cp.async.commit_group;" ::: "memory");
    };

    float acc[4][4][4];
#pragma unroll
    for (int i = 0; i < 4; i++)
#pragma unroll
        for (int j = 0; j < 4; j++)
#pragma unroll
            for (int c = 0; c < 4; c++) acc[i][j][c] = 0.0f;

    const int NS = K >> 5;
    load_stage(0);
    load_stage(1);

    const int g = lane >> 3, r8 = lane & 7;

    for (int j = 0; j < NS; j++) {
        if (j + 1 < NS) {
            asm volatile("cp.async.wait_group 1;" ::: "memory");
        } else {
            asm volatile("cp.async.wait_group 0;" ::: "memory");
        }
        __syncthreads();
        if (j + 2 < NS) load_stage(j + 2);

        uint32_t sb = sbase + (uint32_t)(j % GEMM_STAGES) * STAGE_B;
        uint32_t Ahb = sb, Alb = sb + TQ_, Bhb = sb + 2 * TQ_, Blb = sb + 3 * TQ_;

#pragma unroll
        for (int ks = 0; ks < 2; ks++) {
            uint32_t AH[4][4], AL[4][4];
#pragma unroll
            for (int mt = 0; mt < 4; mt++) {
                int row = wm * 64 + mt * 16 + (g & 1) * 8 + r8;
                uint32_t off = sw64((uint32_t)(row * 64 + ks * 32 + (g >> 1) * 16));
                ldmx4(AH[mt], Ahb + off);
                ldmx4(AL[mt], Alb + off);
            }
#pragma unroll
            for (int np = 0; np < 2; np++) {
                int row = wn * 32 + np * 16 + (g >> 1) * 8 + r8;
                uint32_t off = sw64((uint32_t)(row * 64 + ks * 32 + (g & 1) * 16));
                uint32_t BH[4], BL[4];
                ldmx4(BH, Bhb + off);
                ldmx4(BL, Blb + off);
#pragma unroll
                for (int mt = 0; mt < 4; mt++) {
                    float* c0 = acc[mt][2 * np];
                    float* c1 = acc[mt][2 * np + 1];
                    mma16816(c0, AH[mt], BH[0], BH[1]);
                    mma16816(c0, AH[mt], BL[0], BL[1]);
                    mma16816(c0, AL[mt], BH[0], BH[1]);
                    mma16816(c1, AH[mt], BH[2], BH[3]);
                    mma16816(c1, AH[mt], BL[2], BL[3]);
                    mma16816(c1, AL[mt], BH[2], BH[3]);
                }
            }
        }
    }

    const int er = lane >> 2, ec = (lane & 3) * 2;
#pragma unroll
    for (int mt = 0; mt < 4; mt++) {
#pragma unroll
        for (int nt = 0; nt < 4; nt++) {
            int row = m0 + wm * 64 + mt * 16 + er;
            int col = n0 + wn * 32 + nt * 8 + ec;
            float* c = acc[mt][nt];
            *(float2*)(C + (size_t)row * N + col)       = make_float2(c[0], c[1]);
            *(float2*)(C + (size_t)(row + 8) * N + col) = make_float2(c[2], c[3]);
        }
    }
}

// ---------------------------------------------------------------------------
// Tensor-core causal GQA flash attention — 2 HEADS PER CTA (shared KV loads).
// grid (S/64, H/2, B). 64 queries x 2 heads, 4 warps. 2-stage KV pipeline
// (65536 B) + persistent Q smem for both heads (32768 B) = 98304 -> 2 CTAs/SM.
// Q fragments re-ldmatrix'd per tile per head to bound registers.
// ---------------------------------------------------------------------------
#define AT_TILE 8192
#define AT_STAGE (4 * AT_TILE)                  // 32768
#define AT_SMEM (2 * AT_STAGE + 4 * AT_TILE)    // 98304

__global__ __launch_bounds__(128, 2) void attn_mma(
    const __nv_bfloat16* __restrict__ qh, const __nv_bfloat16* __restrict__ ql,
    const __nv_bfloat16* __restrict__ kh, const __nv_bfloat16* __restrict__ kl,
    const __nv_bfloat16* __restrict__ vh, const __nv_bfloat16* __restrict__ vl,
    __nv_bfloat16* __restrict__ oh, __nv_bfloat16* __restrict__ ol) {
    extern __shared__ char sm[];
    const uint32_t sb = smem_u32(sm);
    const int tid = threadIdx.x, wid = tid >> 5, lane = tid & 31;
    const int qblk = gridDim.x - 1 - blockIdx.x;   // longest-first
    const int hp = blockIdx.y, b = blockIdx.z;
    const int h0 = hp * 2;          // heads h0, h0+1 (same KV group: REP=4)
    const int g = h0 >> 2;
    const int q0 = qblk * 64;
    const uint32_t sQ = sb + 2 * AT_STAGE;  // Qh0,Ql0,Qh1,Ql1 (8192 each)
    const int nT = q0 / 64 + 1;
    const int g2 = lane >> 3, r8v = lane & 7;

    auto load_kv = [&](int t) {
        uint32_t s0 = sb + (uint32_t)(t & 1) * AT_STAGE;
        const __nv_bfloat16* srcs[4] = {kh, kl, vh, vl};
#pragma unroll
        for (int a = 0; a < 4; a++) {
            const __nv_bfloat16* src = srcs[a];
            uint32_t tb = s0 + a * AT_TILE;
#pragma unroll
            for (int it = 0; it < 4; it++) {
                int i = tid + it * 128;
                int r = i >> 3, c = i & 7;
                cp16(tb + r * 128 + ((c ^ (r & 7)) * 16),
                     src + ((size_t)(b * S_ + t * 64 + r) * KV_ + g) * HD_ + c * 8);
            }
        }
        asm volatile("cp.async.commit_group;" ::: "memory");
    };
    load_kv(0);

    // Q tiles for both heads (hi/lo), swizzled, persistent
    for (int i = tid; i < 1024; i += 128) {
        int hh = i >> 9, j = i & 511;
        int r = j >> 3, c = j & 7;
        size_t gidx = ((size_t)(b * S_ + q0 + r) * H_ + h0 + hh) * HD_ + c * 8;
        uint32_t off = r * 128 + ((c ^ (r & 7)) * 16);
        *(uint4*)(sm + (sQ - sb) + hh * 16384 + off)        = *(const uint4*)(qh + gidx);
        *(uint4*)(sm + (sQ - sb) + hh * 16384 + 8192 + off) = *(const uint4*)(ql + gidx);
    }
    __syncthreads();

    float accO[2][8][4];
#pragma unroll
    for (int hh = 0; hh < 2; hh++)
#pragma unroll
        for (int i = 0; i < 8; i++)
#pragma unroll
            for (int c = 0; c < 4; c++) accO[hh][i][c] = 0.0f;
    float mr0[2] = {-1e30f, -1e30f}, mr1[2] = {-1e30f, -1e30f};
    float lr0[2] = {0.0f, 0.0f},     lr1[2] = {0.0f, 0.0f};
    const int qrow0 = q0 + wid * 16 + (lane >> 2);

    for (int t = 0; t < nT; t++) {
        asm volatile("cp.async.wait_group 0;" ::: "memory");
        __syncthreads();
        if (t + 1 < nT) load_kv(t + 1);   // buffer (t+1)&1: compute t-1 done (sync)

        uint32_t st = sb + (uint32_t)(t & 1) * AT_STAGE;
        uint32_t sKh = st, sKl = st + AT_TILE, sVh = st + 2 * AT_TILE, sVl = st + 3 * AT_TILE;

#pragma unroll
        for (int hh = 0; hh < 2; hh++) {
            // Q fragments for this head (from persistent smem)
            uint32_t AH[4][4], AL[4][4];
#pragma unroll
            for (int ks = 0; ks < 4; ks++) {
                int row = wid * 16 + (g2 & 1) * 8 + r8v;
                int ch = ks * 2 + (g2 >> 1);
                uint32_t off = row * 128 + ((ch ^ (row & 7)) * 16);
                ldmx4(AH[ks], sQ + hh * 16384 + off);
                ldmx4(AL[ks], sQ + hh * 16384 + 8192 + off);
            }

            float sc[8][4];
#pragma unroll
            for (int i = 0; i < 8; i++)
#pragma unroll
                for (int c = 0; c < 4; c++) sc[i][c] = 0.0f;
#pragma unroll
            for (int ks = 0; ks < 4; ks++) {
                uint32_t KH[4][4], KL[4][4];
#pragma unroll
                for (int np = 0; np < 4; np++) {
                    int row = np * 16 + (g2 >> 1) * 8 + r8v;
                    int ch = ks * 2 + (g2 & 1);
                    uint32_t off = row * 128 + ((ch ^ (row & 7)) * 16);
                    ldmx4(KH[np], sKh + off);
                    ldmx4(KL[np], sKl + off);
                }
#pragma unroll
                for (int np = 0; np < 4; np++) {
                    mma16816(sc[2 * np],     AH[ks], KH[np][0], KH[np][1]);
                    mma16816(sc[2 * np],     AH[ks], KL[np][0], KL[np][1]);
                    mma16816(sc[2 * np],     AL[ks], KH[np][0], KH[np][1]);
                    mma16816(sc[2 * np + 1], AH[ks], KH[np][2], KH[np][3]);
                    mma16816(sc[2 * np + 1], AH[ks], KL[np][2], KL[np][3]);
                    mma16816(sc[2 * np + 1], AL[ks], KH[np][2], KH[np][3]);
                }
            }

            if (t == nT - 1) {
#pragma unroll
                for (int nt = 0; nt < 8; nt++) {
                    int key = t * 64 + nt * 8 + (lane & 3) * 2;
                    if (key     > qrow0)     sc[nt][0] = -1e30f;
                    if (key + 1 > qrow0)     sc[nt][1] = -1e30f;
                    if (key     > qrow0 + 8) sc[nt][2] = -1e30f;
                    if (key + 1 > qrow0 + 8) sc[nt][3] = -1e30f;
                }
            }

            float mx0 = -1e30f, mx1 = -1e30f;
#pragma unroll
            for (int nt = 0; nt < 8; nt++) {
                mx0 = fmaxf(mx0, fmaxf(sc[nt][0], sc[nt][1]));
                mx1 = fmaxf(mx1, fmaxf(sc[nt][2], sc[nt][3]));
            }
            mx0 = fmaxf(mx0, __shfl_xor_sync(0xffffffffu, mx0, 1));
            mx0 = fmaxf(mx0, __shfl_xor_sync(0xffffffffu, mx0, 2));
            mx1 = fmaxf(mx1, __shfl_xor_sync(0xffffffffu, mx1, 1));
            mx1 = fmaxf(mx1, __shfl_xor_sync(0xffffffffu, mx1, 2));
            float mn0 = fmaxf(mr0[hh], mx0), mn1 = fmaxf(mr1[hh], mx1);
            float cor0 = __expf(mr0[hh] - mn0), cor1 = __expf(mr1[hh] - mn1);
            mr0[hh] = mn0; mr1[hh] = mn1;
            lr0[hh] *= cor0; lr1[hh] *= cor1;
#pragma unroll
            for (int nt = 0; nt < 8; nt++) {
                accO[hh][nt][0] *= cor0; accO[hh][nt][1] *= cor0;
                accO[hh][nt][2] *= cor1; accO[hh][nt][3] *= cor1;
            }

            uint32_t PH[4][4], PL[4][4];
#pragma unroll
            for (int nt = 0; nt < 8; nt++) {
                float e0 = __expf(sc[nt][0] - mn0);
                float e1 = __expf(sc[nt][1] - mn0);
                float e2 = __expf(sc[nt][2] - mn1);
                float e3 = __expf(sc[nt][3] - mn1);
                lr0[hh] += e0 + e1; lr1[hh] += e2 + e3;
                uint32_t h01 = pack2(e0, e1);
                uint32_t h23 = pack2(e2, e3);
                uint32_t l01 = pack2(e0 - bflo(h01), e1 - bfhi(h01));
                uint32_t l23 = pack2(e2 - bflo(h23), e3 - bfhi(h23));
                PH[nt >> 1][(nt & 1) * 2 + 0] = h01;
                PH[nt >> 1][(nt & 1) * 2 + 1] = h23;
                PL[nt >> 1][(nt & 1) * 2 + 0] = l01;
                PL[nt >> 1][(nt & 1) * 2 + 1] = l23;
            }

#pragma unroll
            for (int ks = 0; ks < 4; ks++) {
                uint32_t VH[4][4], VL[4][4];
#pragma unroll
                for (int np = 0; np < 4; np++) {
                    int krow = ks * 16 + (g2 & 1) * 8 + r8v;
                    int ch = np * 2 + (g2 >> 1);
                    uint32_t off = krow * 128 + ((ch ^ (krow & 7)) * 16);
                    ldmx4t(VH[np], sVh + off);
                    ldmx4t(VL[np], sVl + off);
                }
#pragma unroll
                for (int np = 0; np < 4; np++) {
                    mma16816(accO[hh][2 * np],     PH[ks], VH[np][0], VH[np][1]);
                    mma16816(accO[hh][2 * np],     PL[ks], VH[np][0], VH[np][1]);
                    mma16816(accO[hh][2 * np],     PH[ks], VL[np][0], VL[np][1]);
                    mma16816(accO[hh][2 * np + 1], PH[ks], VH[np][2], VH[np][3]);
                    mma16816(accO[hh][2 * np + 1], PL[ks], VH[np][2], VH[np][3]);
                    mma16816(accO[hh][2 * np + 1], PH[ks], VL[np][2], VL[np][3]);
                }
            }
        }
    }

#pragma unroll
    for (int hh = 0; hh < 2; hh++) {
        float l0 = lr0[hh], l1 = lr1[hh];
        l0 += __shfl_xor_sync(0xffffffffu, l0, 1);
        l0 += __shfl_xor_sync(0xffffffffu, l0, 2);
        l1 += __shfl_xor_sync(0xffffffffu, l1, 1);
        l1 += __shfl_xor_sync(0xffffffffu, l1, 2);
        float inv0 = 1.0f / l0, inv1 = 1.0f / l1;

        const int row0 = q0 + wid * 16 + (lane >> 2);
        const int row1 = row0 + 8;
#pragma unroll
        for (int nt = 0; nt < 8; nt++) {
            int col = nt * 8 + (lane & 3) * 2;
            size_t i0 = ((size_t)(b * S_ + row0) * H_ + h0 + hh) * HD_ + col;
            size_t i1 = ((size_t)(b * S_ + row1) * H_ + h0 + hh) * HD_ + col;
            float v0 = accO[hh][nt][0] * inv0, v1 = accO[hh][nt][1] * inv0;
            float v2 = accO[hh][nt][2] * inv1, v3 = accO[hh][nt][3] * inv1;
            uint32_t h01 = pack2(v0, v1);
            uint32_t l01 = pack2(v0 - bflo(h01), v1 - bfhi(h01));
            uint32_t h23 = pack2(v2, v3);
            uint32_t l23 = pack2(v2 - bflo(h23), v3 - bfhi(h23));
            *(uint32_t*)(oh + i0) = h01;
            *(uint32_t*)(ol + i0) = l01;
            *(uint32_t*)(oh + i1) = h23;
            *(uint32_t*)(ol + i1) = l23;
        }
    }
}

// ---------------------------------------------------------------------------
extern "C" void kernel_launch(void* const* d_in, const int* in_sizes, int n_in,
                              void* d_out, int out_size) {
    const float* x  = (const float*)d_in[0];
    const float* fc = (const float*)d_in[1];
    const float* wq = (const float*)d_in[2];
    const float* wk = (const float*)d_in[3];
    const float* wv = (const float*)d_in[4];
    const float* wo = (const float*)d_in[5];
    float* out = (float*)d_out;

    float* qkv;
    cudaGetSymbolAddress((void**)&qkv, g_qkv);
    __nv_bfloat16 *xh, *xl, *wqkvh, *wqkvl, *woh, *wol;
    __nv_bfloat16 *qh, *ql, *khp, *klp, *vhp, *vlp, *oh, *ol;
    cudaGetSymbolAddress((void**)&xh, g_xh);       cudaGetSymbolAddress((void**)&xl, g_xl);
    cudaGetSymbolAddress((void**)&wqkvh, g_wqkvh); cudaGetSymbolAddress((void**)&wqkvl, g_wqkvl);
    cudaGetSymbolAddress((void**)&woh, g_woh);     cudaGetSymbolAddress((void**)&wol, g_wol);
    cudaGetSymbolAddress((void**)&qh, g_qh);       cudaGetSymbolAddress((void**)&ql, g_ql);
    cudaGetSymbolAddress((void**)&khp, g_kh);      cudaGetSymbolAddress((void**)&klp, g_kl);
    cudaGetSymbolAddress((void**)&vhp, g_vh);      cudaGetSymbolAddress((void**)&vlp, g_vl);
    cudaGetSymbolAddress((void**)&oh, g_oh);       cudaGetSymbolAddress((void**)&ol, g_ol);

    cudaFuncSetAttribute(gemm_mma, cudaFuncAttributeMaxDynamicSharedMemorySize, GEMM_SMEM);
    cudaFuncSetAttribute(attn_mma, cudaFuncAttributeMaxDynamicSharedMemorySize, AT_SMEM);

    auto split = [&](const float* src, __nv_bfloat16* h, __nv_bfloat16* l, size_t n) {
        int n4 = (int)(n / 4);
        int grid = (n4 + 1023) / 1024;
        split4_kernel<<<grid, 256>>>((const float4*)src, (uint2*)h, (uint2*)l, n4);
    };
    split(x,  xh,  xl,  (size_t)BS_ * D_);
    split(wq, wqkvh,                           wqkvl,                           (size_t)H_*HD_*D_);
    split(wk, wqkvh + (size_t)H_*HD_*D_,       wqkvl + (size_t)H_*HD_*D_,       (size_t)KV_*HD_*D_);
    split(wv, wqkvh + (size_t)(H_+KV_)*HD_*D_, wqkvl + (size_t)(H_+KV_)*HD_*D_, (size_t)KV_*HD_*D_);
    split(wo, woh, wol, (size_t)D_ * H_ * HD_);

    // Fused QKV projection (plain grid — R14 best)
    gemm_mma<<<dim3(NQKV/128, BS_/128), 256, GEMM_SMEM>>>(xh, xl, wqkvh, wqkvl, qkv,
                                                          BS_, NQKV, D_);

    // RoPE + split (grid-stride x4)
    {
        int qpairs = BS_ * H_ * 32;
        int kpairs = BS_ * KV_ * 32;
        rope_split_strided<<<(qpairs + 1023) / 1024, 256>>>(qkv, fc, (uint32_t*)qh, (uint32_t*)ql,
                                                            H_, NQKV, 0, 0.125f, qpairs);
        rope_split_strided<<<(kpairs + 1023) / 1024, 256>>>(qkv, fc, (uint32_t*)khp, (uint32_t*)klp,
                                                            KV_, NQKV, H_*HD_, 1.0f, kpairs);
        split_strided<<<(kpairs + 1023) / 1024, 256>>>(qkv, (uint32_t*)vhp, (uint32_t*)vlp,
                                                       KV_, NQKV, (H_+KV_)*HD_, kpairs);
    }

    // Tensor-core flash attention, 2 heads/CTA -> oh/ol
    attn_mma<<<dim3(S_/64, H_/2, B_), 128, AT_SMEM>>>(qh, ql, khp, klp, vhp, vlp, oh, ol);

    // Output projection (plain grid)
    gemm_mma<<<dim3(D_/128, BS_/128), 256, GEMM_SMEM>>>(
        oh, ol, woh, wol, out, BS_, D_, D_);
}

// round 17
// speedup vs baseline: 1.0278x; 1.0272x over previous
#include <cuda_runtime.h>
#include <cuda_bf16.h>
#include <math.h>
#include <stdint.h>

// Problem constants
#define B_   2
#define S_   2048
#define D_   2048
#define H_   32
#define KV_  8
#define HD_  64
#define REP_ 4
#define BS_  (B_*S_)
#define NQKV (H_*HD_ + 2*KV_*HD_)      // 3072

// fp32 scratch: fused qkv projection output [BS_, 3072]
__device__ float g_qkv[(size_t)BS_*NQKV];

// bf16 hi/lo scratch
__device__ __nv_bfloat16 g_xh[(size_t)BS_*D_],  g_xl[(size_t)BS_*D_];
__device__ __nv_bfloat16 g_wqkvh[(size_t)NQKV*D_], g_wqkvl[(size_t)NQKV*D_];
__device__ __nv_bfloat16 g_woh[(size_t)D_*H_*HD_],  g_wol[(size_t)D_*H_*HD_];
__device__ __nv_bfloat16 g_qh[(size_t)BS_*H_*HD_],  g_ql[(size_t)BS_*H_*HD_];
__device__ __nv_bfloat16 g_kh[(size_t)BS_*KV_*HD_], g_kl[(size_t)BS_*KV_*HD_];
__device__ __nv_bfloat16 g_vh[(size_t)BS_*KV_*HD_], g_vl[(size_t)BS_*KV_*HD_];
__device__ __nv_bfloat16 g_oh[(size_t)BS_*H_*HD_],  g_ol[(size_t)BS_*H_*HD_];

// ---------------------------------------------------------------------------
__device__ __forceinline__ uint32_t smem_u32(const void* p) {
    uint32_t a;
    asm("{ .reg .u64 t; cvta.to.shared.u64 t, %1; cvt.u32.u64 %0, t; }"
        : "=r"(a) : "l"(p));
    return a;
}
__device__ __forceinline__ void cp16(uint32_t dst, const void* src) {
    asm volatile("cp.async.cg.shared.global [%0], [%1], 16;" :: "r"(dst), "l"(src));
}
__device__ __forceinline__ void ldmx4(uint32_t* r, uint32_t addr) {
    asm volatile("ldmatrix.sync.aligned.m8n8.x4.shared.b16 {%0,%1,%2,%3}, [%4];"
                 : "=r"(r[0]), "=r"(r[1]), "=r"(r[2]), "=r"(r[3]) : "r"(addr));
}
__device__ __forceinline__ void ldmx4t(uint32_t* r, uint32_t addr) {
    asm volatile("ldmatrix.sync.aligned.m8n8.x4.trans.shared.b16 {%0,%1,%2,%3}, [%4];"
                 : "=r"(r[0]), "=r"(r[1]), "=r"(r[2]), "=r"(r[3]) : "r"(addr));
}
__device__ __forceinline__ void mma16816(float* c, const uint32_t* a,
                                         uint32_t b0, uint32_t b1) {
    asm volatile("mma.sync.aligned.m16n8k16.row.col.f32.bf16.bf16.f32 "
                 "{%0,%1,%2,%3}, {%4,%5,%6,%7}, {%8,%9}, {%0,%1,%2,%3};"
                 : "+f"(c[0]), "+f"(c[1]), "+f"(c[2]), "+f"(c[3])
                 : "r"(a[0]), "r"(a[1]), "r"(a[2]), "r"(a[3]), "r"(b0), "r"(b1));
}
__device__ __forceinline__ uint32_t pack2(float lo, float hi) {
    __nv_bfloat162 t = __floats2bfloat162_rn(lo, hi);
    uint32_t u;
    memcpy(&u, &t, 4);
    return u;
}
__device__ __forceinline__ float bflo(uint32_t u) { return __uint_as_float(u << 16); }
__device__ __forceinline__ float bfhi(uint32_t u) { return __uint_as_float(u & 0xffff0000u); }
__device__ __forceinline__ uint32_t sw64(uint32_t off) {
    return off ^ ((off >> 3) & 0x30u);
}

// ---------------------------------------------------------------------------
// Fused 5-segment fp32 -> bf16 hi/lo split (x, wq, wk, wv, wo in ONE launch)
// ---------------------------------------------------------------------------
#define SPN_X  (BS_*D_/4)               // 2097152
#define SPN_WQ (H_*HD_*D_/4)            // 1048576
#define SPN_WK (KV_*HD_*D_/4)           //  262144
#define SPN_C0 SPN_X
#define SPN_C1 (SPN_C0 + SPN_WQ)
#define SPN_C2 (SPN_C1 + SPN_WK)
#define SPN_C3 (SPN_C2 + SPN_WK)
#define SPN_TOT (SPN_C3 + SPN_WQ)       // 4718592

__global__ void split_all_kernel(const float4* __restrict__ x,
                                 const float4* __restrict__ wq,
                                 const float4* __restrict__ wk,
                                 const float4* __restrict__ wv,
                                 const float4* __restrict__ wo,
                                 uint2* __restrict__ xh, uint2* __restrict__ xl,
                                 uint2* __restrict__ wqkvh, uint2* __restrict__ wqkvl,
                                 uint2* __restrict__ woh, uint2* __restrict__ wol) {
    const int span = gridDim.x * blockDim.x;
#pragma unroll 4
    for (int idx = blockIdx.x * blockDim.x + threadIdx.x; idx < SPN_TOT; idx += span) {
        const float4* src;
        uint2 *dh, *dl;
        int li;
        if (idx < SPN_C0)      { li = idx;           src = x;  dh = xh;                 dl = xl; }
        else if (idx < SPN_C1) { li = idx - SPN_C0;  src = wq; dh = wqkvh;              dl = wqkvl; }
        else if (idx < SPN_C2) { li = idx - SPN_C1;  src = wk; dh = wqkvh + SPN_WQ;     dl = wqkvl + SPN_WQ; }
        else if (idx < SPN_C3) { li = idx - SPN_C2;  src = wv; dh = wqkvh + SPN_WQ + SPN_WK; dl = wqkvl + SPN_WQ + SPN_WK; }
        else                   { li = idx - SPN_C3;  src = wo; dh = woh;                dl = wol; }
        float4 v = src[li];
        __nv_bfloat16 h[4], l[4];
        float xs[4] = {v.x, v.y, v.z, v.w};
#pragma unroll
        for (int j = 0; j < 4; j++) {
            h[j] = __float2bfloat16(xs[j]);
            l[j] = __float2bfloat16(xs[j] - __bfloat162float(h[j]));
        }
        uint2 hv, lv;
        memcpy(&hv, h, 8);
        memcpy(&lv, l, 8);
        dh[li] = hv;
        dl[li] = lv;
    }
}

// ---------------------------------------------------------------------------
// Fused rope(q) + rope(k) + split(v) from g_qkv in ONE launch
// ---------------------------------------------------------------------------
#define RP_Q  (BS_*H_*32)               // 4194304
#define RP_K  (BS_*KV_*32)              // 1048576
#define RP_C0 RP_Q
#define RP_C1 (RP_C0 + RP_K)
#define RP_TOT (RP_C1 + RP_K)           // 6291456

__global__ void rope_all_kernel(const float* __restrict__ t, const float* __restrict__ fc,
                                uint32_t* __restrict__ qh, uint32_t* __restrict__ ql,
                                uint32_t* __restrict__ kh, uint32_t* __restrict__ kl,
                                uint32_t* __restrict__ vh, uint32_t* __restrict__ vl) {
    const int span = gridDim.x * blockDim.x;
#pragma unroll 4
    for (int idx = blockIdx.x * blockDim.x + threadIdx.x; idx < RP_TOT; idx += span) {
        int li, per, cb, seg;
        uint32_t *dh, *dl;
        float scale;
        if (idx < RP_C0)      { li = idx;          per = H_ * 32;  cb = 0;              scale = 0.125f; dh = qh; dl = ql; seg = 0; }
        else if (idx < RP_C1) { li = idx - RP_C0;  per = KV_ * 32; cb = H_ * HD_;       scale = 1.0f;   dh = kh; dl = kl; seg = 1; }
        else                  { li = idx - RP_C1;  per = KV_ * 32; cb = (H_+KV_) * HD_; scale = 1.0f;   dh = vh; dl = vl; seg = 2; }
        int bs = li / per, pr = li - bs * per;
        float2 v = *(const float2*)(t + (size_t)bs * NQKV + cb + pr * 2);
        float r0, r1;
        if (seg < 2) {
            int p = pr & 31;
            int s = bs & (S_ - 1);
            float c  = fc[(s * 32 + p) * 2 + 0];
            float sn = fc[(s * 32 + p) * 2 + 1];
            r0 = (v.x * c - v.y * sn) * scale;
            r1 = (v.x * sn + v.y * c) * scale;
        } else {
            r0 = v.x; r1 = v.y;
        }
        uint32_t hp = pack2(r0, r1);
        uint32_t lp = pack2(r0 - bflo(hp), r1 - bfhi(hp));
        dh[li] = hp;
        dl[li] = lp;
    }
}

// ---------------------------------------------------------------------------
// bf16x3 GEMM via mma.sync (R13/R14 version — best).
// CTA tile 128x128, 256 threads (8 warps, 2Mx4N, warp 64x32), BK=32.
// SW64 smem, 3 stages = 98304 B -> depth 3 AND 2 CTAs/SM. Plain grid.
// ---------------------------------------------------------------------------
#define TQ_   (128 * 64)
#define STAGE_B  (4 * TQ_)               // 32768
#define GEMM_STAGES 3
#define GEMM_SMEM (GEMM_STAGES * STAGE_B)   // 98304

__global__ __launch_bounds__(256, 2) void gemm_mma(
    const __nv_bfloat16* __restrict__ Ah, const __nv_bfloat16* __restrict__ Al,
    const __nv_bfloat16* __restrict__ Bh, const __nv_bfloat16* __restrict__ Bl,
    float* __restrict__ C, int M, int N, int K) {
    extern __shared__ char sm[];
    const uint32_t sbase = smem_u32(sm);

    const int tid  = threadIdx.x;
    const int wid  = tid >> 5;
    const int lane = tid & 31;
    const int wm   = wid >> 2;
    const int wn   = wid & 3;
    const int m0   = blockIdx.y << 7;
    const int n0   = blockIdx.x << 7;

    const __nv_bfloat16* srcs[4] = {Ah, Al, Bh, Bl};
    const int rows0[4] = {m0, m0, n0, n0};

    auto load_stage = [&](int j) {
        uint32_t sb = sbase + (uint32_t)(j % GEMM_STAGES) * STAGE_B;
        int k0 = j << 5;
#pragma unroll
        for (int t = 0; t < 4; t++) {
            const __nv_bfloat16* src = srcs[t] + (size_t)rows0[t] * K + k0;
            uint32_t tb = sb + t * TQ_;
#pragma unroll
            for (int it = 0; it < 2; it++) {
                int ch = tid + it * 256;
                int r = ch >> 2, c4 = ch & 3;
                cp16(tb + sw64((uint32_t)(r * 64 + c4 * 16)),
                     src + (size_t)r * K + c4 * 8);
            }
        }
        asm volatile("cp.async.commit_group;" ::: "memory");
    };

    float acc[4][4][4];
#pragma unroll
    for (int i = 0; i < 4; i++)
#pragma unroll
        for (int j = 0; j < 4; j++)
#pragma unroll
            for (int c = 0; c < 4; c++) acc[i][j][c] = 0.0f;

    const int NS = K >> 5;
    load_stage(0);
    load_stage(1);

    const int g = lane >> 3, r8 = lane & 7;

    for (int j = 0; j < NS; j++) {
        if (j + 1 < NS) {
            asm volatile("cp.async.wait_group 1;" ::: "memory");
        } else {
            asm volatile("cp.async.wait_group 0;" ::: "memory");
        }
        __syncthreads();
        if (j + 2 < NS) load_stage(j + 2);

        uint32_t sb = sbase + (uint32_t)(j % GEMM_STAGES) * STAGE_B;
        uint32_t Ahb = sb, Alb = sb + TQ_, Bhb = sb + 2 * TQ_, Blb = sb + 3 * TQ_;

#pragma unroll
        for (int ks = 0; ks < 2; ks++) {
            uint32_t AH[4][4], AL[4][4];
#pragma unroll
            for (int mt = 0; mt < 4; mt++) {
                int row = wm * 64 + mt * 16 + (g & 1) * 8 + r8;
                uint32_t off = sw64((uint32_t)(row * 64 + ks * 32 + (g >> 1) * 16));
                ldmx4(AH[mt], Ahb + off);
                ldmx4(AL[mt], Alb + off);
            }
#pragma unroll
            for (int np = 0; np < 2; np++) {
                int row = wn * 32 + np * 16 + (g >> 1) * 8 + r8;
                uint32_t off = sw64((uint32_t)(row * 64 + ks * 32 + (g & 1) * 16));
                uint32_t BH[4], BL[4];
                ldmx4(BH, Bhb + off);
                ldmx4(BL, Blb + off);
#pragma unroll
                for (int mt = 0; mt < 4; mt++) {
                    float* c0 = acc[mt][2 * np];
                    float* c1 = acc[mt][2 * np + 1];
                    mma16816(c0, AH[mt], BH[0], BH[1]);
                    mma16816(c0, AH[mt], BL[0], BL[1]);
                    mma16816(c0, AL[mt], BH[0], BH[1]);
                    mma16816(c1, AH[mt], BH[2], BH[3]);
                    mma16816(c1, AH[mt], BL[2], BL[3]);
                    mma16816(c1, AL[mt], BH[2], BH[3]);
                }
            }
        }
    }

    const int er = lane >> 2, ec = (lane & 3) * 2;
#pragma unroll
    for (int mt = 0; mt < 4; mt++) {
#pragma unroll
        for (int nt = 0; nt < 4; nt++) {
            int row = m0 + wm * 64 + mt * 16 + er;
            int col = n0 + wn * 32 + nt * 8 + ec;
            float* c = acc[mt][nt];
            *(float2*)(C + (size_t)row * N + col)       = make_float2(c[0], c[1]);
            *(float2*)(C + (size_t)(row + 8) * N + col) = make_float2(c[2], c[3]);
        }
    }
}

// ---------------------------------------------------------------------------
// Tensor-core causal GQA flash attention (R14 version — best).
// 64 queries/CTA (4 warps), 3-stage KV pipeline with Q overlaid on stage 2.
// 98304 B -> 2 CTAs/SM.
// ---------------------------------------------------------------------------
#define AT_TILE 8192
#define AT_STAGE (4 * AT_TILE)             // 32768
#define AT_STAGES 3
#define AT_SMEM (AT_STAGES * AT_STAGE)     // 98304

__global__ __launch_bounds__(128, 2) void attn_mma(
    const __nv_bfloat16* __restrict__ qh, const __nv_bfloat16* __restrict__ ql,
    const __nv_bfloat16* __restrict__ kh, const __nv_bfloat16* __restrict__ kl,
    const __nv_bfloat16* __restrict__ vh, const __nv_bfloat16* __restrict__ vl,
    __nv_bfloat16* __restrict__ oh, __nv_bfloat16* __restrict__ ol) {
    extern __shared__ char sm[];
    const uint32_t sb = smem_u32(sm);
    const int tid = threadIdx.x, wid = tid >> 5, lane = tid & 31;
    const int qblk = gridDim.x - 1 - blockIdx.x;
    const int h = blockIdx.y, b = blockIdx.z, g = h >> 2;
    const int q0 = qblk * 64;
    const uint32_t sQh = sb + 2 * AT_STAGE;
    const uint32_t sQl = sQh + AT_TILE;
    const int nT = q0 / 64 + 1;
    const int g2 = lane >> 3, r8v = lane & 7;

    auto load_kv = [&](int t) {
        uint32_t s0 = sb + (uint32_t)(t % AT_STAGES) * AT_STAGE;
        const __nv_bfloat16* srcs[4] = {kh, kl, vh, vl};
#pragma unroll
        for (int a = 0; a < 4; a++) {
            const __nv_bfloat16* src = srcs[a];
            uint32_t tb = s0 + a * AT_TILE;
#pragma unroll
            for (int it = 0; it < 4; it++) {
                int i = tid + it * 128;
                int r = i >> 3, c = i & 7;
                cp16(tb + r * 128 + ((c ^ (r & 7)) * 16),
                     src + ((size_t)(b * S_ + t * 64 + r) * KV_ + g) * HD_ + c * 8);
            }
        }
        asm volatile("cp.async.commit_group;" ::: "memory");
    };
    load_kv(0);
    if (nT > 1) load_kv(1);

    for (int i = tid; i < 512; i += 128) {
        int r = i >> 3, c = i & 7;
        size_t gidx = ((size_t)(b * S_ + q0 + r) * H_ + h) * HD_ + c * 8;
        uint32_t off = r * 128 + ((c ^ (r & 7)) * 16);
        *(uint4*)(sm + (sQh - sb) + off) = *(const uint4*)(qh + gidx);
        *(uint4*)(sm + (sQl - sb) + off) = *(const uint4*)(ql + gidx);
    }
    __syncthreads();

    uint32_t AH[4][4], AL[4][4];
#pragma unroll
    for (int ks = 0; ks < 4; ks++) {
        int row = wid * 16 + (g2 & 1) * 8 + r8v;
        int ch = ks * 2 + (g2 >> 1);
        uint32_t off = row * 128 + ((ch ^ (row & 7)) * 16);
        ldmx4(AH[ks], sQh + off);
        ldmx4(AL[ks], sQl + off);
    }

    float accO[8][4];
#pragma unroll
    for (int i = 0; i < 8; i++)
#pragma unroll
        for (int c = 0; c < 4; c++) accO[i][c] = 0.0f;
    float mrow0 = -1e30f, mrow1 = -1e30f, lrow0 = 0.0f, lrow1 = 0.0f;
    const int qrow0 = q0 + wid * 16 + (lane >> 2);

    for (int t = 0; t < nT; t++) {
        if (t + 1 < nT) {
            asm volatile("cp.async.wait_group 1;" ::: "memory");
        } else {
            asm volatile("cp.async.wait_group 0;" ::: "memory");
        }
        __syncthreads();
        if (t + 2 < nT) load_kv(t + 2);

        uint32_t st = sb + (uint32_t)(t % AT_STAGES) * AT_STAGE;
        uint32_t sKh = st, sKl = st + AT_TILE, sVh = st + 2 * AT_TILE, sVl = st + 3 * AT_TILE;

        float sc[8][4];
#pragma unroll
        for (int i = 0; i < 8; i++)
#pragma unroll
            for (int c = 0; c < 4; c++) sc[i][c] = 0.0f;
#pragma unroll
        for (int ks = 0; ks < 4; ks++) {
            uint32_t KH[4][4], KL[4][4];
#pragma unroll
            for (int np = 0; np < 4; np++) {
                int row = np * 16 + (g2 >> 1) * 8 + r8v;
                int ch = ks * 2 + (g2 & 1);
                uint32_t off = row * 128 + ((ch ^ (row & 7)) * 16);
                ldmx4(KH[np], sKh + off);
                ldmx4(KL[np], sKl + off);
            }
#pragma unroll
            for (int np = 0; np < 4; np++) {
                mma16816(sc[2 * np],     AH[ks], KH[np][0], KH[np][1]);
                mma16816(sc[2 * np],     AH[ks], KL[np][0], KL[np][1]);
                mma16816(sc[2 * np],     AL[ks], KH[np][0], KH[np][1]);
                mma16816(sc[2 * np + 1], AH[ks], KH[np][2], KH[np][3]);
                mma16816(sc[2 * np + 1], AH[ks], KL[np][2], KL[np][3]);
                mma16816(sc[2 * np + 1], AL[ks], KH[np][2], KH[np][3]);
            }
        }

        if (t == nT - 1) {
#pragma unroll
            for (int nt = 0; nt < 8; nt++) {
                int key = t * 64 + nt * 8 + (lane & 3) * 2;
                if (key     > qrow0)     sc[nt][0] = -1e30f;
                if (key + 1 > qrow0)     sc[nt][1] = -1e30f;
                if (key     > qrow0 + 8) sc[nt][2] = -1e30f;
                if (key + 1 > qrow0 + 8) sc[nt][3] = -1e30f;
            }
        }

        float mx0 = -1e30f, mx1 = -1e30f;
#pragma unroll
        for (int nt = 0; nt < 8; nt++) {
            mx0 = fmaxf(mx0, fmaxf(sc[nt][0], sc[nt][1]));
            mx1 = fmaxf(mx1, fmaxf(sc[nt][2], sc[nt][3]));
        }
        mx0 = fmaxf(mx0, __shfl_xor_sync(0xffffffffu, mx0, 1));
        mx0 = fmaxf(mx0, __shfl_xor_sync(0xffffffffu, mx0, 2));
        mx1 = fmaxf(mx1, __shfl_xor_sync(0xffffffffu, mx1, 1));
        mx1 = fmaxf(mx1, __shfl_xor_sync(0xffffffffu, mx1, 2));
        float mn0 = fmaxf(mrow0, mx0), mn1 = fmaxf(mrow1, mx1);
        float cor0 = __expf(mrow0 - mn0), cor1 = __expf(mrow1 - mn1);
        mrow0 = mn0; mrow1 = mn1;
        lrow0 *= cor0; lrow1 *= cor1;
#pragma unroll
        for (int nt = 0; nt < 8; nt++) {
            accO[nt][0] *= cor0; accO[nt][1] *= cor0;
            accO[nt][2] *= cor1; accO[nt][3] *= cor1;
        }

        uint32_t PH[4][4], PL[4][4];
#pragma unroll
        for (int nt = 0; nt < 8; nt++) {
            float e0 = __expf(sc[nt][0] - mrow0);
            float e1 = __expf(sc[nt][1] - mrow0);
            float e2 = __expf(sc[nt][2] - mrow1);
            float e3 = __expf(sc[nt][3] - mrow1);
            lrow0 += e0 + e1; lrow1 += e2 + e3;
            uint32_t h01 = pack2(e0, e1);
            uint32_t h23 = pack2(e2, e3);
            uint32_t l01 = pack2(e0 - bflo(h01), e1 - bfhi(h01));
            uint32_t l23 = pack2(e2 - bflo(h23), e3 - bfhi(h23));
            PH[nt >> 1][(nt & 1) * 2 + 0] = h01;
            PH[nt >> 1][(nt & 1) * 2 + 1] = h23;
            PL[nt >> 1][(nt & 1) * 2 + 0] = l01;
            PL[nt >> 1][(nt & 1) * 2 + 1] = l23;
        }

#pragma unroll
        for (int ks = 0; ks < 4; ks++) {
            uint32_t VH[4][4], VL[4][4];
#pragma unroll
            for (int np = 0; np < 4; np++) {
                int krow = ks * 16 + (g2 & 1) * 8 + r8v;
                int ch = np * 2 + (g2 >> 1);
                uint32_t off = krow * 128 + ((ch ^ (krow & 7)) * 16);
                ldmx4t(VH[np], sVh + off);
                ldmx4t(VL[np], sVl + off);
            }
#pragma unroll
            for (int np = 0; np < 4; np++) {
                mma16816(accO[2 * np],     PH[ks], VH[np][0], VH[np][1]);
                mma16816(accO[2 * np],     PL[ks], VH[np][0], VH[np][1]);
                mma16816(accO[2 * np],     PH[ks], VL[np][0], VL[np][1]);
                mma16816(accO[2 * np + 1], PH[ks], VH[np][2], VH[np][3]);
                mma16816(accO[2 * np + 1], PL[ks], VH[np][2], VH[np][3]);
                mma16816(accO[2 * np + 1], PH[ks], VL[np][2], VL[np][3]);
            }
        }
    }

    lrow0 += __shfl_xor_sync(0xffffffffu, lrow0, 1);
    lrow0 += __shfl_xor_sync(0xffffffffu, lrow0, 2);
    lrow1 += __shfl_xor_sync(0xffffffffu, lrow1, 1);
    lrow1 += __shfl_xor_sync(0xffffffffu, lrow1, 2);
    float inv0 = 1.0f / lrow0, inv1 = 1.0f / lrow1;

    const int row0 = q0 + wid * 16 + (lane >> 2);
    const int row1 = row0 + 8;
#pragma unroll
    for (int nt = 0; nt < 8; nt++) {
        int col = nt * 8 + (lane & 3) * 2;
        size_t i0 = ((size_t)(b * S_ + row0) * H_ + h) * HD_ + col;
        size_t i1 = ((size_t)(b * S_ + row1) * H_ + h) * HD_ + col;
        float v0 = accO[nt][0] * inv0, v1 = accO[nt][1] * inv0;
        float v2 = accO[nt][2] * inv1, v3 = accO[nt][3] * inv1;
        uint32_t h01 = pack2(v0, v1);
        uint32_t l01 = pack2(v0 - bflo(h01), v1 - bfhi(h01));
        uint32_t h23 = pack2(v2, v3);
        uint32_t l23 = pack2(v2 - bflo(h23), v3 - bfhi(h23));
        *(uint32_t*)(oh + i0) = h01;
        *(uint32_t*)(ol + i0) = l01;
        *(uint32_t*)(oh + i1) = h23;
        *(uint32_t*)(ol + i1) = l23;
    }
}

// ---------------------------------------------------------------------------
extern "C" void kernel_launch(void* const* d_in, const int* in_sizes, int n_in,
                              void* d_out, int out_size) {
    const float* x  = (const float*)d_in[0];
    const float* fc = (const float*)d_in[1];
    const float* wq = (const float*)d_in[2];
    const float* wk = (const float*)d_in[3];
    const float* wv = (const float*)d_in[4];
    const float* wo = (const float*)d_in[5];
    float* out = (float*)d_out;

    float* qkv;
    cudaGetSymbolAddress((void**)&qkv, g_qkv);
    __nv_bfloat16 *xh, *xl, *wqkvh, *wqkvl, *woh, *wol;
    __nv_bfloat16 *qh, *ql, *khp, *klp, *vhp, *vlp, *oh, *ol;
    cudaGetSymbolAddress((void**)&xh, g_xh);       cudaGetSymbolAddress((void**)&xl, g_xl);
    cudaGetSymbolAddress((void**)&wqkvh, g_wqkvh); cudaGetSymbolAddress((void**)&wqkvl, g_wqkvl);
    cudaGetSymbolAddress((void**)&woh, g_woh);     cudaGetSymbolAddress((void**)&wol, g_wol);
    cudaGetSymbolAddress((void**)&qh, g_qh);       cudaGetSymbolAddress((void**)&ql, g_ql);
    cudaGetSymbolAddress((void**)&khp, g_kh);      cudaGetSymbolAddress((void**)&klp, g_kl);
    cudaGetSymbolAddress((void**)&vhp, g_vh);      cudaGetSymbolAddress((void**)&vlp, g_vl);
    cudaGetSymbolAddress((void**)&oh, g_oh);       cudaGetSymbolAddress((void**)&ol, g_ol);

    cudaFuncSetAttribute(gemm_mma, cudaFuncAttributeMaxDynamicSharedMemorySize, GEMM_SMEM);
    cudaFuncSetAttribute(attn_mma, cudaFuncAttributeMaxDynamicSharedMemorySize, AT_SMEM);

    // ONE fused split launch (x, wq, wk, wv, wo)
    split_all_kernel<<<(SPN_TOT + 1023) / 1024, 256>>>(
        (const float4*)x, (const float4*)wq, (const float4*)wk,
        (const float4*)wv, (const float4*)wo,
        (uint2*)xh, (uint2*)xl, (uint2*)wqkvh, (uint2*)wqkvl, (uint2*)woh, (uint2*)wol);

    // Fused QKV projection
    gemm_mma<<<dim3(NQKV/128, BS_/128), 256, GEMM_SMEM>>>(xh, xl, wqkvh, wqkvl, qkv,
                                                          BS_, NQKV, D_);

    // ONE fused rope(q)+rope(k)+split(v) launch
    rope_all_kernel<<<(RP_TOT + 1023) / 1024, 256>>>(
        qkv, fc, (uint32_t*)qh, (uint32_t*)ql, (uint32_t*)khp, (uint32_t*)klp,
        (uint32_t*)vhp, (uint32_t*)vlp);

    // Tensor-core flash attention -> oh/ol
    attn_mma<<<dim3(S_/64, H_, B_), 128, AT_SMEM>>>(qh, ql, khp, klp, vhp, vlp, oh, ol);

    // Output projection
    gemm_mma<<<dim3(D_/128, BS_/128), 256, GEMM_SMEM>>>(
        oh, ol, woh, wol, out, BS_, D_, D_);
}